// round 2
// baseline (speedup 1.0000x reference)
#include <cuda_runtime.h>

// ---------------------------------------------------------------------------
// STARDNN: scene-conditioned MLP  512 -> 512 -> 256 -> 64,  B = 16384, 7 scenes
// out[b] = L2( relu(L1( relu(L0(x[b])) )) ),  Lk(h) = h @ (Wk[s]*gWk) + bk[s] + gbk
//
// Algorithm: bucket rows by scene, per-scene tiled SGEMM (fp32), gather on the
// first layer, scatter on the last.
// ---------------------------------------------------------------------------

#define NS    7
#define MAXB  16384
#define D0    512
#define D1    512
#define D2    256
#define D3    64

// scratch (allocation-free: __device__ globals)
__device__ int   g_count[NS];
__device__ int   g_offset[NS];
__device__ int   g_cursor[NS];
__device__ int   g_perm[MAXB];
__device__ float g_h1[MAXB * D1];
__device__ float g_h2[MAXB * D2];
__device__ float g_SW0[NS * D0 * D1];
__device__ float g_SW1[NS * D1 * D2];
__device__ float g_SW2[NS * D2 * D3];

// Scene may be materialized as int32 or int64 by the harness (reference says
// int64, but JAX w/o x64 emits int32). Values are 1..7, so for int64 data the
// int32 word at index 1 is the high half of scene[0] == 0; for int32 data it
// is a scene value >= 1. One load disambiguates.
__device__ __forceinline__ int scene_at(const int* __restrict__ p, int b, bool is64) {
    int v = is64 ? p[2 * b] : p[b];
    int s = v - 1;
    // clamp: wrong values fail correctness visibly instead of corrupting memory
    return (s < 0) ? 0 : (s >= NS ? NS - 1 : s);
}

// ---------------------------------------------------------------------------
__global__ void k_init() {
    if (threadIdx.x < NS) g_count[threadIdx.x] = 0;
}

__global__ void k_count(const int* __restrict__ scene, int B) {
    int b = blockIdx.x * blockDim.x + threadIdx.x;
    if (b < B) {
        bool is64 = (scene[1] == 0);
        atomicAdd(&g_count[scene_at(scene, b, is64)], 1);
    }
}

__global__ void k_scan() {
    int off = 0;
    for (int s = 0; s < NS; s++) {
        g_offset[s] = off;
        g_cursor[s] = off;
        off += g_count[s];
    }
}

__global__ void k_scatter(const int* __restrict__ scene, int B) {
    int b = blockIdx.x * blockDim.x + threadIdx.x;
    if (b < B) {
        bool is64 = (scene[1] == 0);
        int s = scene_at(scene, b, is64);
        int pos = atomicAdd(&g_cursor[s], 1);
        g_perm[pos] = b;
    }
}

// Pre-scale all weights: SW[s][i][o] = W[s][i][o] * gW[0][i][o]
__global__ void k_scale_all(const float* __restrict__ W0, const float* __restrict__ gW0,
                            const float* __restrict__ W1, const float* __restrict__ gW1,
                            const float* __restrict__ W2, const float* __restrict__ gW2) {
    int stride = gridDim.x * blockDim.x;
    int t = blockIdx.x * blockDim.x + threadIdx.x;
    for (int j = t; j < D0 * D1; j += stride) {
        float g = gW0[j];
#pragma unroll
        for (int s = 0; s < NS; s++) g_SW0[s * D0 * D1 + j] = W0[s * D0 * D1 + j] * g;
    }
    for (int j = t; j < D1 * D2; j += stride) {
        float g = gW1[j];
#pragma unroll
        for (int s = 0; s < NS; s++) g_SW1[s * D1 * D2 + j] = W1[s * D1 * D2 + j] * g;
    }
    for (int j = t; j < D2 * D3; j += stride) {
        float g = gW2[j];
#pragma unroll
        for (int s = 0; s < NS; s++) g_SW2[s * D2 * D3 + j] = W2[s * D2 * D3 + j] * g;
    }
}

// ---------------------------------------------------------------------------
// Tiled SGEMM over one scene bucket.
//   LAYER 0: in = x (gather via perm)   -> g_h1 (permuted), K=512, N=512, relu
//   LAYER 1: in = g_h1 (permuted)       -> g_h2 (permuted), K=512, N=256, relu
//   LAYER 2: in = g_h2 (permuted)       -> out (scatter via perm), K=256, N=64
// Tile: BM=BN=64, BK=16; 256 threads (16x16), 4x4 accumulators per thread.
// ---------------------------------------------------------------------------
template <int LAYER, int K, int N, bool RELU>
__global__ __launch_bounds__(256) void k_gemm(const float* __restrict__ xin,
                                              float* __restrict__ xout,
                                              const float* __restrict__ bias,
                                              const float* __restrict__ gbias) {
    constexpr int BM = 64, BN = 64, BK = 16;
    constexpr bool GATHER  = (LAYER == 0);
    constexpr bool SCATTER = (LAYER == 2);

    const int s   = blockIdx.z;
    const int cnt = g_count[s];
    const int m0  = blockIdx.x * BM;
    if (m0 >= cnt) return;
    const int off  = g_offset[s];
    const int rows = min(BM, cnt - m0);
    const int n0   = blockIdx.y * BN;

    const float* in  = (LAYER == 0) ? xin : (LAYER == 1 ? g_h1 : g_h2);
    float*       out = (LAYER == 2) ? xout : (LAYER == 0 ? g_h1 : g_h2);
    const float* SW  = (LAYER == 0) ? g_SW0 : (LAYER == 1 ? g_SW1 : g_SW2);

    __shared__ float As[BK][BM];   // transposed A tile
    __shared__ float Bs[BK][BN];

    const int tx  = threadIdx.x;   // 0..15
    const int ty  = threadIdx.y;   // 0..15
    const int tid = ty * 16 + tx;

    // A-tile load mapping: thread -> (row, k-quad)
    const int ar  = tid >> 2;          // 0..63
    const int akq = (tid & 3) * 4;     // 0,4,8,12
    int agrow = -1;
    if (ar < rows) {
        int prow = off + m0 + ar;
        agrow = GATHER ? g_perm[prow] : prow;
    }
    // B-tile load mapping: thread -> (k, n-quad)
    const int bk = tid >> 4;           // 0..15
    const int bn = (tid & 15) * 4;     // 0..60
    const float* Bbase = SW + (size_t)s * K * N + (size_t)bk * N + n0 + bn;

    float acc[4][4];
#pragma unroll
    for (int i = 0; i < 4; i++)
#pragma unroll
        for (int j = 0; j < 4; j++) acc[i][j] = 0.f;

    for (int k0 = 0; k0 < K; k0 += BK) {
        float4 av = make_float4(0.f, 0.f, 0.f, 0.f);
        if (agrow >= 0)
            av = *(const float4*)(in + (size_t)agrow * K + k0 + akq);
        As[akq + 0][ar] = av.x;
        As[akq + 1][ar] = av.y;
        As[akq + 2][ar] = av.z;
        As[akq + 3][ar] = av.w;

        *(float4*)&Bs[bk][bn] = *(const float4*)(Bbase + (size_t)k0 * N);
        __syncthreads();

#pragma unroll
        for (int kk = 0; kk < BK; kk++) {
            float4 a = *(const float4*)&As[kk][ty * 4];
            float4 b = *(const float4*)&Bs[kk][tx * 4];
            acc[0][0] += a.x * b.x; acc[0][1] += a.x * b.y; acc[0][2] += a.x * b.z; acc[0][3] += a.x * b.w;
            acc[1][0] += a.y * b.x; acc[1][1] += a.y * b.y; acc[1][2] += a.y * b.z; acc[1][3] += a.y * b.w;
            acc[2][0] += a.z * b.x; acc[2][1] += a.z * b.y; acc[2][2] += a.z * b.z; acc[2][3] += a.z * b.w;
            acc[3][0] += a.w * b.x; acc[3][1] += a.w * b.y; acc[3][2] += a.w * b.z; acc[3][3] += a.w * b.w;
        }
        __syncthreads();
    }

    // epilogue: + bias[s] + gbias, optional relu, store (scatter on last layer)
    const int c = n0 + tx * 4;
    float4 bb  = *(const float4*)(bias + (size_t)s * N + c);
    float4 gbv = *(const float4*)(gbias + c);
    bb.x += gbv.x; bb.y += gbv.y; bb.z += gbv.z; bb.w += gbv.w;

#pragma unroll
    for (int i = 0; i < 4; i++) {
        int r = ty * 4 + i;
        if (r < rows) {
            int prow = off + m0 + r;
            int orow = SCATTER ? g_perm[prow] : prow;
            float4 v;
            v.x = acc[i][0] + bb.x;
            v.y = acc[i][1] + bb.y;
            v.z = acc[i][2] + bb.z;
            v.w = acc[i][3] + bb.w;
            if (RELU) {
                v.x = fmaxf(v.x, 0.f);
                v.y = fmaxf(v.y, 0.f);
                v.z = fmaxf(v.z, 0.f);
                v.w = fmaxf(v.w, 0.f);
            }
            *(float4*)(out + (size_t)orow * N + c) = v;
        }
    }
}

// ---------------------------------------------------------------------------
extern "C" void kernel_launch(void* const* d_in, const int* in_sizes, int n_in,
                              void* d_out, int out_size) {
    const float* x     = (const float*)d_in[0];
    const int*   scene = (const int*)d_in[1];   // int32 or int64, auto-detected
    const float* W0  = (const float*)d_in[2];
    const float* b0  = (const float*)d_in[3];
    const float* gW0 = (const float*)d_in[4];
    const float* gb0 = (const float*)d_in[5];
    const float* W1  = (const float*)d_in[6];
    const float* b1  = (const float*)d_in[7];
    const float* gW1 = (const float*)d_in[8];
    const float* gb1 = (const float*)d_in[9];
    const float* W2  = (const float*)d_in[10];
    const float* b2  = (const float*)d_in[11];
    const float* gW2 = (const float*)d_in[12];
    const float* gb2 = (const float*)d_in[13];
    float* out = (float*)d_out;

    const int B = in_sizes[1];              // 16384 (scene element count)
    const int mtiles = (B + 63) / 64;       // covers worst case (one scene owns all)

    k_init<<<1, 32>>>();
    k_count<<<(B + 255) / 256, 256>>>(scene, B);
    k_scan<<<1, 1>>>();
    k_scatter<<<(B + 255) / 256, 256>>>(scene, B);
    k_scale_all<<<1024, 256>>>(W0, gW0, W1, gW1, W2, gW2);

    dim3 blk(16, 16);
    k_gemm<0, D0, D1, true ><<<dim3(mtiles, D1 / 64, NS), blk>>>(x,  nullptr, b0, gb0);
    k_gemm<1, D1, D2, true ><<<dim3(mtiles, D2 / 64, NS), blk>>>(nullptr, nullptr, b1, gb1);
    k_gemm<2, D2, D3, false><<<dim3(mtiles, D3 / 64, NS), blk>>>(nullptr, out, b2, gb2);
}

// round 7
// speedup vs baseline: 1.9449x; 1.9449x over previous
#include <cuda_runtime.h>
#include <cuda_bf16.h>
#include <cstdint>

// ---------------------------------------------------------------------------
// STARDNN on GB300. R7: R2-proven scaffolding (bucketing + fp32 prescaled
// weights + fp32 activations) with an mma.sync bf16x3 GEMM core.
// All bf16 splitting happens inside the GEMM at stage time; fragments are
// built with plain shared loads (no ldmatrix, no cp.async).
// ---------------------------------------------------------------------------

#define NS    7
#define MAXB  16384
#define D0    512
#define D1    512
#define D2    256
#define D3    64

// scratch (allocation-free: __device__ globals) — identical set to R2 (passed)
__device__ int   g_count[NS];
__device__ int   g_offset[NS];
__device__ int   g_cursor[NS];
__device__ int   g_perm[MAXB];
__device__ float g_h1[MAXB * D1];
__device__ float g_h2[MAXB * D2];
__device__ float g_SW0[NS * D0 * D1];
__device__ float g_SW1[NS * D1 * D2];
__device__ float g_SW2[NS * D2 * D3];

// ------------------------------ helpers ------------------------------------
#define MMA_BF16(d, a, b) \
    asm volatile("mma.sync.aligned.m16n8k16.row.col.f32.bf16.bf16.f32 " \
                 "{%0,%1,%2,%3}, {%4,%5,%6,%7}, {%8,%9}, {%0,%1,%2,%3};" \
                 : "+f"((d)[0]), "+f"((d)[1]), "+f"((d)[2]), "+f"((d)[3]) \
                 : "r"((a)[0]), "r"((a)[1]), "r"((a)[2]), "r"((a)[3]), \
                   "r"((b)[0]), "r"((b)[1]))

__device__ __forceinline__ void bsplit(float v, __nv_bfloat16& h, __nv_bfloat16& l) {
    h = __float2bfloat16(v);
    l = __float2bfloat16(v - __bfloat162float(h));
}

__device__ __forceinline__ uint32_t pack2(__nv_bfloat16 a, __nv_bfloat16 b) {
    union { __nv_bfloat16 h[2]; uint32_t u; } t;
    t.h[0] = a; t.h[1] = b;
    return t.u;
}

// split a float4 into hi/lo packed uint2
__device__ __forceinline__ void split4(float4 v, uint2& hi, uint2& lo) {
    __nv_bfloat16 h0, l0, h1, l1, h2, l2, h3, l3;
    bsplit(v.x, h0, l0); bsplit(v.y, h1, l1);
    bsplit(v.z, h2, l2); bsplit(v.w, h3, l3);
    hi.x = pack2(h0, h1); hi.y = pack2(h2, h3);
    lo.x = pack2(l0, l1); lo.y = pack2(l2, l3);
}

// ------------------------------ bucketing (verbatim R2) --------------------
__device__ __forceinline__ int scene_at(const int* __restrict__ p, int b, bool is64) {
    int v = is64 ? p[2 * b] : p[b];
    int s = v - 1;
    return (s < 0) ? 0 : (s >= NS ? NS - 1 : s);
}

__global__ void k_init() {
    if (threadIdx.x < NS) g_count[threadIdx.x] = 0;
}

__global__ void k_count(const int* __restrict__ scene, int B) {
    int b = blockIdx.x * blockDim.x + threadIdx.x;
    if (b < B) {
        bool is64 = (scene[1] == 0);
        atomicAdd(&g_count[scene_at(scene, b, is64)], 1);
    }
}

__global__ void k_scan() {
    int off = 0;
    for (int s = 0; s < NS; s++) {
        g_offset[s] = off;
        g_cursor[s] = off;
        off += g_count[s];
    }
}

__global__ void k_scatter(const int* __restrict__ scene, int B) {
    int b = blockIdx.x * blockDim.x + threadIdx.x;
    if (b < B) {
        bool is64 = (scene[1] == 0);
        int s = scene_at(scene, b, is64);
        int pos = atomicAdd(&g_cursor[s], 1);
        g_perm[pos] = b;
    }
}

// Pre-scale all weights (verbatim R2): SW[s][k][n] = W[s][k][n] * gW[k][n]
__global__ void k_scale_all(const float* __restrict__ W0, const float* __restrict__ gW0,
                            const float* __restrict__ W1, const float* __restrict__ gW1,
                            const float* __restrict__ W2, const float* __restrict__ gW2) {
    int stride = gridDim.x * blockDim.x;
    int t = blockIdx.x * blockDim.x + threadIdx.x;
    for (int j = t; j < D0 * D1; j += stride) {
        float g = gW0[j];
#pragma unroll
        for (int s = 0; s < NS; s++) g_SW0[s * D0 * D1 + j] = W0[s * D0 * D1 + j] * g;
    }
    for (int j = t; j < D1 * D2; j += stride) {
        float g = gW1[j];
#pragma unroll
        for (int s = 0; s < NS; s++) g_SW1[s * D1 * D2 + j] = W1[s * D1 * D2 + j] * g;
    }
    for (int j = t; j < D2 * D3; j += stride) {
        float g = gW2[j];
#pragma unroll
        for (int s = 0; s < NS; s++) g_SW2[s * D2 * D3 + j] = W2[s * D2 * D3 + j] * g;
    }
}

// ------------------------------ mma GEMM -----------------------------------
// CTA: 128 x BN tile of one scene bucket (grid: mtiles x ntiles x NS, early
// return like R2). K in chunks of 16.  In-kernel bf16 hi/lo split at stage.
// A smem: [128][16] bf16 rows, ROWB=48 (32B data + 16B pad) hi/lo planes.
// B smem: [16][BN] bf16 rows, BROWB=BN*2+16, hi/lo planes.
// Fragments via plain 32/16-bit shared loads. 8 warps = 2 x 4 (WM=64, WN=BN/4).
template <int LAYER, int K, int NF, int BN, bool RELU>
__global__ __launch_bounds__(256) void k_gemm(const float* __restrict__ xin,
                                              float* __restrict__ xout,
                                              const float* __restrict__ bias,
                                              const float* __restrict__ gbias,
                                              int B) {
    constexpr int MI = 4;                 // WM=64 -> 4 m16 tiles
    constexpr int NI = BN / 4 / 8;        // WN=BN/4 -> NI n8 tiles
    constexpr int NCH = K / 16;
    constexpr int ROWB = 48;
    constexpr int APL = 128 * ROWB;       // 6144
    constexpr int BROWB = BN * 2 + 16;
    constexpr int BPL = 16 * BROWB;
    constexpr int BUFSZ = 2 * APL + 2 * BPL;
    constexpr int BPT = BN / 64;          // B float4 loads per thread (2 or 1)

    extern __shared__ char sm[];

    const int s   = blockIdx.z;
    const int cnt = g_count[s];
    const int m0  = blockIdx.x * 128;
    if (m0 >= cnt) return;
    const int off  = g_offset[s];
    const int rows = min(128, cnt - m0);
    const int n0   = blockIdx.y * BN;
    const int tid  = threadIdx.x;

    const float* in = (LAYER == 0) ? xin : (LAYER == 1 ? g_h1 : g_h2);
    float*      out = (LAYER == 2) ? xout : (LAYER == 0 ? g_h1 : g_h2);
    const float* SW = (LAYER == 0) ? g_SW0 : (LAYER == 1 ? g_SW1 : g_SW2);

    // ---- per-thread stage descriptors (k0 advances each chunk) ----
    // A: 512 float4 per chunk -> 2 per thread (rows tid>>2 and 64+(tid>>2))
    const int aq = (tid & 3) * 4;                        // float col 0,4,8,12
    const float* aptr[2];
    uint32_t adst[2];
#pragma unroll
    for (int i = 0; i < 2; i++) {
        int r = (tid >> 2) + i * 64;
        int pr = off + m0 + ((r < rows) ? r : 0);        // clamp dead rows
        if (pr > B - 1) pr = B - 1;
        int grow = (LAYER == 0) ? g_perm[pr] : pr;
        aptr[i] = in + (size_t)grow * K + aq;
        adst[i] = (uint32_t)r * ROWB + aq * 2;
    }
    // B: 16*BN/4 float4 per chunk -> BPT per thread
    const float* bptr[BPT];
    uint32_t bdst[BPT];
#pragma unroll
    for (int i = 0; i < BPT; i++) {
        int j = tid + i * 256;
        int krow = j / (BN / 4);
        int ncol = (j % (BN / 4)) * 4;
        bptr[i] = SW + ((size_t)s * K + krow) * NF + n0 + ncol;
        bdst[i] = (uint32_t)krow * BROWB + ncol * 2;
    }

    const int lane = tid & 31, w = tid >> 5;
    const int wm = (w >> 2) * 64;                        // 2 warp rows
    const int wn = (w & 3) * (BN / 4);                   // 4 warp cols
    const int g  = lane >> 2, tg = lane & 3;

    float acc[MI][NI][4];
#pragma unroll
    for (int mi = 0; mi < MI; mi++)
#pragma unroll
        for (int ni = 0; ni < NI; ni++)
#pragma unroll
            for (int e = 0; e < 4; e++) acc[mi][ni][e] = 0.f;

    float4 aS[2], bS[BPT];

    // ---- prologue: stage chunk 0 into buffer 0 ----
#pragma unroll
    for (int i = 0; i < 2; i++) aS[i] = *(const float4*)(aptr[i]);
#pragma unroll
    for (int i = 0; i < BPT; i++) bS[i] = *(const float4*)(bptr[i]);
#pragma unroll
    for (int i = 0; i < 2; i++) {
        uint2 hi, lo;
        split4(aS[i], hi, lo);
        *(uint2*)(sm + adst[i])       = hi;
        *(uint2*)(sm + adst[i] + APL) = lo;
    }
#pragma unroll
    for (int i = 0; i < BPT; i++) {
        uint2 hi, lo;
        split4(bS[i], hi, lo);
        *(uint2*)(sm + 2 * APL + bdst[i])       = hi;
        *(uint2*)(sm + 2 * APL + bdst[i] + BPL) = lo;
    }
    __syncthreads();

    for (int c = 0; c < NCH; c++) {
        // prefetch chunk c+1 (global latency overlaps the mma below)
        if (c + 1 < NCH) {
            const int k1 = (c + 1) * 16;
#pragma unroll
            for (int i = 0; i < 2; i++) aS[i] = *(const float4*)(aptr[i] + k1);
#pragma unroll
            for (int i = 0; i < BPT; i++) bS[i] = *(const float4*)(bptr[i] + (size_t)k1 * NF);
        }

        const char* Ab = sm + (c & 1) * BUFSZ;
        const char* Bb = Ab + 2 * APL;

        // A fragments (hi and lo planes): plain lds.32
        uint32_t ah[MI][4], al[MI][4];
#pragma unroll
        for (int mi = 0; mi < MI; mi++) {
            uint32_t base = (uint32_t)(wm + mi * 16 + g) * ROWB + 4 * tg;
            ah[mi][0] = *(const uint32_t*)(Ab + base);
            ah[mi][1] = *(const uint32_t*)(Ab + base + 8 * ROWB);
            ah[mi][2] = *(const uint32_t*)(Ab + base + 16);
            ah[mi][3] = *(const uint32_t*)(Ab + base + 8 * ROWB + 16);
            al[mi][0] = *(const uint32_t*)(Ab + base + APL);
            al[mi][1] = *(const uint32_t*)(Ab + base + APL + 8 * ROWB);
            al[mi][2] = *(const uint32_t*)(Ab + base + APL + 16);
            al[mi][3] = *(const uint32_t*)(Ab + base + APL + 8 * ROWB + 16);
        }
        // B fragments: pairs of 16-bit loads (k rows, n cols)
        uint32_t bh[NI][2], bl[NI][2];
#pragma unroll
        for (int ni = 0; ni < NI; ni++) {
            uint32_t cb = 2u * (wn + ni * 8 + g);
#pragma unroll
            for (int pl = 0; pl < 2; pl++) {
                const char* P = Bb + pl * BPL + cb;
                uint32_t x0 = *(const unsigned short*)(P + (2 * tg) * BROWB);
                uint32_t x1 = *(const unsigned short*)(P + (2 * tg + 1) * BROWB);
                uint32_t x2 = *(const unsigned short*)(P + (2 * tg + 8) * BROWB);
                uint32_t x3 = *(const unsigned short*)(P + (2 * tg + 9) * BROWB);
                if (pl == 0) { bh[ni][0] = x0 | (x1 << 16); bh[ni][1] = x2 | (x3 << 16); }
                else         { bl[ni][0] = x0 | (x1 << 16); bl[ni][1] = x2 | (x3 << 16); }
            }
        }
#pragma unroll
        for (int mi = 0; mi < MI; mi++)
#pragma unroll
            for (int ni = 0; ni < NI; ni++) {
                MMA_BF16(acc[mi][ni], ah[mi], bh[ni]);
                MMA_BF16(acc[mi][ni], ah[mi], bl[ni]);
                MMA_BF16(acc[mi][ni], al[mi], bh[ni]);
            }

        // store prefetched chunk into the other buffer
        if (c + 1 < NCH) {
            char* D = sm + ((c + 1) & 1) * BUFSZ;
#pragma unroll
            for (int i = 0; i < 2; i++) {
                uint2 hi, lo;
                split4(aS[i], hi, lo);
                *(uint2*)(D + adst[i])       = hi;
                *(uint2*)(D + adst[i] + APL) = lo;
            }
#pragma unroll
            for (int i = 0; i < BPT; i++) {
                uint2 hi, lo;
                split4(bS[i], hi, lo);
                *(uint2*)(D + 2 * APL + bdst[i])       = hi;
                *(uint2*)(D + 2 * APL + bdst[i] + BPL) = lo;
            }
        }
        __syncthreads();
    }

    // ----------------------------- epilogue --------------------------------
    const float* bs = bias + (size_t)s * NF + n0;
    const float* gb = gbias + n0;
#pragma unroll
    for (int mi = 0; mi < MI; mi++) {
        const int rbase = wm + mi * 16 + g;
#pragma unroll
        for (int ni = 0; ni < NI; ni++) {
            const int c0 = wn + ni * 8 + 2 * tg;
            const float bv0 = bs[c0] + gb[c0];
            const float bv1 = bs[c0 + 1] + gb[c0 + 1];
#pragma unroll
            for (int half = 0; half < 2; half++) {
                const int r = rbase + half * 8;
                if (r < rows) {
                    float v0 = acc[mi][ni][half * 2 + 0] + bv0;
                    float v1 = acc[mi][ni][half * 2 + 1] + bv1;
                    if (RELU) { v0 = fmaxf(v0, 0.f); v1 = fmaxf(v1, 0.f); }
                    const int prow = off + m0 + r;
                    const int orow = (LAYER == 2) ? g_perm[prow] : prow;
                    *(float2*)(out + (size_t)orow * NF + n0 + c0) = make_float2(v0, v1);
                }
            }
        }
    }
}

// ---------------------------------------------------------------------------
extern "C" void kernel_launch(void* const* d_in, const int* in_sizes, int n_in,
                              void* d_out, int out_size) {
    const float* x     = (const float*)d_in[0];
    const int*   scene = (const int*)d_in[1];   // int32 or int64, auto-detected
    const float* W0  = (const float*)d_in[2];
    const float* b0  = (const float*)d_in[3];
    const float* gW0 = (const float*)d_in[4];
    const float* gb0 = (const float*)d_in[5];
    const float* W1  = (const float*)d_in[6];
    const float* b1  = (const float*)d_in[7];
    const float* gW1 = (const float*)d_in[8];
    const float* gb1 = (const float*)d_in[9];
    const float* W2  = (const float*)d_in[10];
    const float* b2  = (const float*)d_in[11];
    const float* gW2 = (const float*)d_in[12];
    const float* gb2 = (const float*)d_in[13];
    float* out = (float*)d_out;

    const int B = in_sizes[1];
    const int mtiles = (B + 127) / 128;

    // smem: L0/L1: 2*(2*6144 + 2*16*272) = 41984; L2: 2*(2*6144 + 2*16*144) = 33792
    const int SM_L01 = 2 * (2 * 128 * 48 + 2 * 16 * (128 * 2 + 16));
    const int SM_L2  = 2 * (2 * 128 * 48 + 2 * 16 * (64 * 2 + 16));

    k_init<<<1, 32>>>();
    k_count<<<(B + 255) / 256, 256>>>(scene, B);
    k_scan<<<1, 1>>>();
    k_scatter<<<(B + 255) / 256, 256>>>(scene, B);
    k_scale_all<<<1024, 256>>>(W0, gW0, W1, gW1, W2, gW2);

    k_gemm<0, D0, D1, 128, true ><<<dim3(mtiles, D1 / 128, NS), 256, SM_L01>>>(
        x, nullptr, b0, gb0, B);
    k_gemm<1, D1, D2, 128, true ><<<dim3(mtiles, D2 / 128, NS), 256, SM_L01>>>(
        nullptr, nullptr, b1, gb1, B);
    k_gemm<2, D2, D3, 64, false><<<dim3(mtiles, 1, NS), 256, SM_L2>>>(
        nullptr, out, b2, gb2, B);
}